// round 8
// baseline (speedup 1.0000x reference)
#include <cuda_runtime.h>
#include <cstdint>

#define NUM_SMS     152
#define CTAS_PER_SM 4
#define NUM_BLOCKS  (NUM_SMS * CTAS_PER_SM)   // 608
#define NUM_THREADS 512
#define CHUNK_F4    (NUM_THREADS * 2)         // 1024 float4 per chunk (2x unroll)

// Self-resetting cross-launch state (graph-replay safe, no init kernel):
__device__ float        g_sum;
__device__ unsigned int g_cnt;
__device__ unsigned int g_work;     // dynamic chunk counter
__device__ unsigned int g_ticket;   // retire ticket

__global__ void __launch_bounds__(NUM_THREADS, CTAS_PER_SM) dlwm_fused_kernel(
    const float4* __restrict__ out,
    const float4* __restrict__ lbl0,
    const float4* __restrict__ lbl1,
    float* __restrict__ d_out,
    int n4)
{
    const int n_chunks = (n4 + CHUNK_F4 - 1) / CHUNK_F4;

    float acc = 0.0f;
    unsigned int cnt = 0;

    __shared__ unsigned int s_chunk;

    // Initial grab.
    if (threadIdx.x == 0) s_chunk = atomicAdd(&g_work, 1u);
    __syncthreads();
    unsigned int chunk = s_chunk;

    while (chunk < (unsigned int)n_chunks) {
        // Prefetch next chunk index; the ~318cyc atomic overlaps the 6 loads.
        if (threadIdx.x == 0) s_chunk = atomicAdd(&g_work, 1u);

        int base = (int)chunk * CHUNK_F4 + threadIdx.x;
        int i0 = base;
        int i1 = base + NUM_THREADS;

        if (i1 < n4) {
            float4 o0 = __ldg(out  + i0);
            float4 a0 = __ldg(lbl0 + i0);
            float4 b0 = __ldg(lbl1 + i0);
            float4 o1 = __ldg(out  + i1);
            float4 a1 = __ldg(lbl0 + i1);
            float4 b1 = __ldg(lbl1 + i1);

            acc += fabsf(o0.x - a0.x) * b0.x;
            acc += fabsf(o0.y - a0.y) * b0.y;
            acc += fabsf(o0.z - a0.z) * b0.z;
            acc += fabsf(o0.w - a0.w) * b0.w;
            acc += fabsf(o1.x - a1.x) * b1.x;
            acc += fabsf(o1.y - a1.y) * b1.y;
            acc += fabsf(o1.z - a1.z) * b1.z;
            acc += fabsf(o1.w - a1.w) * b1.w;

            cnt += (a0.x != 0.0f) + (a0.y != 0.0f) + (a0.z != 0.0f) + (a0.w != 0.0f);
            cnt += (a1.x != 0.0f) + (a1.y != 0.0f) + (a1.z != 0.0f) + (a1.w != 0.0f);
        } else {
            // Remainder chunk (not hit for n4 % CHUNK_F4 == 0, kept for safety).
            if (i0 < n4) {
                float4 o = __ldg(out  + i0);
                float4 a = __ldg(lbl0 + i0);
                float4 b = __ldg(lbl1 + i0);
                acc += fabsf(o.x - a.x) * b.x;
                acc += fabsf(o.y - a.y) * b.y;
                acc += fabsf(o.z - a.z) * b.z;
                acc += fabsf(o.w - a.w) * b.w;
                cnt += (a.x != 0.0f) + (a.y != 0.0f) + (a.z != 0.0f) + (a.w != 0.0f);
            }
        }

        __syncthreads();          // s_chunk write visible + all lanes done
        chunk = s_chunk;
    }

    // ---- intra-block reduction ----
    #pragma unroll
    for (int off = 16; off > 0; off >>= 1) {
        acc += __shfl_down_sync(0xFFFFFFFFu, acc, off);
        cnt += __shfl_down_sync(0xFFFFFFFFu, cnt, off);
    }

    __shared__ float        s_acc[NUM_THREADS / 32];
    __shared__ unsigned int s_cnt[NUM_THREADS / 32];
    const int lane = threadIdx.x & 31;
    const int wid  = threadIdx.x >> 5;
    if (lane == 0) { s_acc[wid] = acc; s_cnt[wid] = cnt; }
    __syncthreads();

    if (wid == 0) {
        acc = (lane < (NUM_THREADS / 32)) ? s_acc[lane] : 0.0f;
        cnt = (lane < (NUM_THREADS / 32)) ? s_cnt[lane] : 0u;
        #pragma unroll
        for (int off = 8; off > 0; off >>= 1) {
            acc += __shfl_down_sync(0xFFFFFFFFu, acc, off);
            cnt += __shfl_down_sync(0xFFFFFFFFu, cnt, off);
        }
        if (lane == 0) {
            // Relaxed scalar accumulation — no fence, no L1 flush.
            atomicAdd(&g_sum, acc);
            atomicAdd(&g_cnt, cnt);

            // acq_rel ticket: release orders the adds; acquire lets the
            // last arriver observe every block's adds.
            unsigned int ticket;
            asm volatile(
                "atom.acq_rel.gpu.global.add.u32 %0, [%1], %2;"
                : "=r"(ticket)
                : "l"(&g_ticket), "r"(1u)
                : "memory");

            if (ticket == gridDim.x - 1) {
                float        fsum = atomicAdd(&g_sum, 0.0f);
                unsigned int csum = atomicAdd(&g_cnt, 0u);
                d_out[0] = (csum == 0u) ? 0.0f : (fsum / (float)csum);
                // Self-clean for the next graph replay.
                atomicExch(&g_sum, 0.0f);
                atomicExch(&g_cnt, 0u);
                atomicExch(&g_work, 0u);
                atomicExch(&g_ticket, 0u);
            }
        }
    }
}

extern "C" void kernel_launch(void* const* d_in, const int* in_sizes, int n_in,
                              void* d_out, int out_size)
{
    const float4* out_t = (const float4*)d_in[0];
    const float4* lbl0  = (const float4*)d_in[1];
    const float4* lbl1  = (const float4*)d_in[2];
    const int n  = in_sizes[0];   // 15,728,640 (divisible by 4)
    const int n4 = n >> 2;

    int blocks = NUM_BLOCKS;
    int max_blocks = (n4 + NUM_THREADS - 1) / NUM_THREADS;
    if (blocks > max_blocks) blocks = max_blocks;

    dlwm_fused_kernel<<<blocks, NUM_THREADS>>>(out_t, lbl0, lbl1, (float*)d_out, n4);
}